// round 6
// baseline (speedup 1.0000x reference)
#include <cuda_runtime.h>

#define BATCH 8
#define NROWS 10000
#define CDIM 256
#define CHUNKS 125
#define ROWS_PER_CHUNK 80   // 10000 / 125; 80 = 16*5, no tail
#define LN_EPS 1e-5f

// Scratch (allocation-free rule: __device__ globals)
__device__ float g_partial[BATCH][CHUNKS][CDIM];
__device__ float g_agg[BATCH][CDIM];

// ---------------------------------------------------------------------------
// Kernel 1: partial column sums. grid (BATCH, CHUNKS) = 1000 blocks, 256 thr.
// Thread t: float4-column (t&63), row-group (t>>6). 4 independent
// accumulators, 4 loads issued per iteration (rows r+rg, +4, +8, +12),
// 5 iterations covering 80 rows.
// ---------------------------------------------------------------------------
__global__ void col_sum_kernel(const float* __restrict__ x) {
    const int b = blockIdx.x;
    const int ch = blockIdx.y;
    const int t = threadIdx.x;
    const int qc = t & 63;       // float4 column 0..63
    const int rg = t >> 6;       // row group 0..3

    const float4* base = (const float4*)(x
        + ((size_t)b * NROWS + (size_t)ch * ROWS_PER_CHUNK) * CDIM) + qc;

    float4 a0 = make_float4(0.f, 0.f, 0.f, 0.f);
    float4 a1 = make_float4(0.f, 0.f, 0.f, 0.f);
    float4 a2 = make_float4(0.f, 0.f, 0.f, 0.f);
    float4 a3 = make_float4(0.f, 0.f, 0.f, 0.f);
#pragma unroll
    for (int r = 0; r < ROWS_PER_CHUNK; r += 16) {
        float4 v0 = base[(size_t)(r + rg) * 64];
        float4 v1 = base[(size_t)(r + rg + 4) * 64];
        float4 v2 = base[(size_t)(r + rg + 8) * 64];
        float4 v3 = base[(size_t)(r + rg + 12) * 64];
        a0.x += v0.x; a0.y += v0.y; a0.z += v0.z; a0.w += v0.w;
        a1.x += v1.x; a1.y += v1.y; a1.z += v1.z; a1.w += v1.w;
        a2.x += v2.x; a2.y += v2.y; a2.z += v2.z; a2.w += v2.w;
        a3.x += v3.x; a3.y += v3.y; a3.z += v3.z; a3.w += v3.w;
    }
    a0.x += a1.x + a2.x + a3.x;
    a0.y += a1.y + a2.y + a3.y;
    a0.z += a1.z + a2.z + a3.z;
    a0.w += a1.w + a2.w + a3.w;

    __shared__ float4 sh[256];
    sh[t] = a0;
    __syncthreads();
    if (t < 64) {
        float4 a = sh[t];
        float4 c1 = sh[t + 64];
        float4 c2 = sh[t + 128];
        float4 c3 = sh[t + 192];
        a.x += c1.x + c2.x + c3.x;
        a.y += c1.y + c2.y + c3.y;
        a.z += c1.z + c2.z + c3.z;
        a.w += c1.w + c2.w + c3.w;
        ((float4*)&g_partial[b][ch][0])[t] = a;
    }
}

// ---------------------------------------------------------------------------
// Kernel 2: finish mean + tiny GEMM  agg[b][c] = dot(mean[b,:], W[c,:]) + bias
// ---------------------------------------------------------------------------
__global__ void mean_gemm_kernel(const float* __restrict__ W,
                                 const float* __restrict__ bias) {
    const int b = blockIdx.x;
    const int t = threadIdx.x;
    __shared__ float smean[CDIM];

    float s = 0.0f;
#pragma unroll 5
    for (int j = 0; j < CHUNKS; ++j) s += g_partial[b][j][t];
    smean[t] = s * (1.0f / (float)NROWS);
    __syncthreads();

    const int warp = t >> 5;
    const int lane = t & 31;
    for (int c = warp; c < CDIM; c += 8) {
        const float* wr = W + (size_t)c * CDIM;
        float d = 0.0f;
#pragma unroll
        for (int k = lane; k < CDIM; k += 32) {
            d += wr[k] * smean[k];
        }
#pragma unroll
        for (int off = 16; off > 0; off >>= 1)
            d += __shfl_down_sync(0xffffffffu, d, off);
        if (lane == 0) g_agg[b][c] = d + bias[c];
    }
}

// ---------------------------------------------------------------------------
// Kernel 3: fused residual + LayerNorm. One warp handles FOUR rows -> 8
// independent 16B loads in flight per lane (128B). x read with __ldcs
// (last use, demote from L2), out written with __stcs (streaming, evict-
// first) so the L2-resident x from pass 1 survives.
// Block = 128 threads = 4 warps = 16 rows; 10000 = 16*625 so no block
// crosses a batch boundary. grid = 80000/16 = 5000 blocks.
// ---------------------------------------------------------------------------
__global__ void resid_ln_kernel(const float* __restrict__ x,
                                const float* __restrict__ gamma,
                                const float* __restrict__ beta,
                                float* __restrict__ out) {
    const int t = threadIdx.x;
    const int warp = t >> 5;
    const int lane = t & 31;
    const long row0 = (long)blockIdx.x * 16 + warp * 4;
    const int b = (int)(row0 / NROWS);   // same for all 16 rows in the block

    __shared__ float sh_agg[CDIM];
    __shared__ float sh_g[CDIM];
    __shared__ float sh_b[CDIM];
    sh_agg[t] = g_agg[b][t];
    sh_agg[t + 128] = g_agg[b][t + 128];
    sh_g[t] = gamma[t];
    sh_g[t + 128] = gamma[t + 128];
    sh_b[t] = beta[t];
    sh_b[t + 128] = beta[t + 128];
    __syncthreads();

    // 8 independent global loads issued back-to-back
    float4 xs[4][2];
#pragma unroll
    for (int rr = 0; rr < 4; ++rr) {
        const float4* xr = (const float4*)(x + (row0 + rr) * (long)CDIM);
        xs[rr][0] = __ldcs(&xr[lane * 2 + 0]);
        xs[rr][1] = __ldcs(&xr[lane * 2 + 1]);
    }

    float4 ag0 = ((const float4*)sh_agg)[lane * 2 + 0];
    float4 ag1 = ((const float4*)sh_agg)[lane * 2 + 1];

    float y[4][8];
    float s[4], ss[4];
#pragma unroll
    for (int rr = 0; rr < 4; ++rr) {
        y[rr][0] = xs[rr][0].x + ag0.x; y[rr][1] = xs[rr][0].y + ag0.y;
        y[rr][2] = xs[rr][0].z + ag0.z; y[rr][3] = xs[rr][0].w + ag0.w;
        y[rr][4] = xs[rr][1].x + ag1.x; y[rr][5] = xs[rr][1].y + ag1.y;
        y[rr][6] = xs[rr][1].z + ag1.z; y[rr][7] = xs[rr][1].w + ag1.w;
        float a = 0.f, q = 0.f;
#pragma unroll
        for (int i = 0; i < 8; ++i) { a += y[rr][i]; q += y[rr][i] * y[rr][i]; }
        s[rr] = a; ss[rr] = q;
    }

#pragma unroll
    for (int off = 16; off > 0; off >>= 1) {
#pragma unroll
        for (int rr = 0; rr < 4; ++rr) {
            s[rr]  += __shfl_xor_sync(0xffffffffu, s[rr], off);
            ss[rr] += __shfl_xor_sync(0xffffffffu, ss[rr], off);
        }
    }

    const float inv = 1.0f / (float)CDIM;
    float mu[4], rs[4];
#pragma unroll
    for (int rr = 0; rr < 4; ++rr) {
        mu[rr] = s[rr] * inv;
        rs[rr] = rsqrtf(ss[rr] * inv - mu[rr] * mu[rr] + LN_EPS);
    }

    float4 g0 = ((const float4*)sh_g)[lane * 2 + 0];
    float4 g1 = ((const float4*)sh_g)[lane * 2 + 1];
    float4 b0 = ((const float4*)sh_b)[lane * 2 + 0];
    float4 b1 = ((const float4*)sh_b)[lane * 2 + 1];

#pragma unroll
    for (int rr = 0; rr < 4; ++rr) {
        float4* orow = (float4*)(out + (row0 + rr) * (long)CDIM);
        float4 o;
        o.x = (y[rr][0] - mu[rr]) * rs[rr] * g0.x + b0.x;
        o.y = (y[rr][1] - mu[rr]) * rs[rr] * g0.y + b0.y;
        o.z = (y[rr][2] - mu[rr]) * rs[rr] * g0.z + b0.z;
        o.w = (y[rr][3] - mu[rr]) * rs[rr] * g0.w + b0.w;
        __stcs(&orow[lane * 2 + 0], o);
        o.x = (y[rr][4] - mu[rr]) * rs[rr] * g1.x + b1.x;
        o.y = (y[rr][5] - mu[rr]) * rs[rr] * g1.y + b1.y;
        o.z = (y[rr][6] - mu[rr]) * rs[rr] * g1.z + b1.z;
        o.w = (y[rr][7] - mu[rr]) * rs[rr] * g1.w + b1.w;
        __stcs(&orow[lane * 2 + 1], o);
    }
}

extern "C" void kernel_launch(void* const* d_in, const int* in_sizes, int n_in,
                              void* d_out, int out_size) {
    const float* x     = (const float*)d_in[0];
    const float* W     = (const float*)d_in[1];
    const float* bias  = (const float*)d_in[2];
    const float* gamma = (const float*)d_in[3];
    const float* beta  = (const float*)d_in[4];
    float* out = (float*)d_out;

    dim3 g1(BATCH, CHUNKS);
    col_sum_kernel<<<g1, 256>>>(x);
    mean_gemm_kernel<<<BATCH, CDIM>>>(W, bias);
    resid_ln_kernel<<<(BATCH * NROWS) / 16, 128>>>(x, gamma, beta, out);
}

// round 7
// speedup vs baseline: 1.0914x; 1.0914x over previous
#include <cuda_runtime.h>

#define BATCH 8
#define NROWS 10000
#define CDIM 256
#define CHUNKS 100
#define ROWS_PER_CHUNK 100   // 10000 / 100
#define LN_EPS 1e-5f

// Scratch (allocation-free rule: __device__ globals)
__device__ float g_partial[BATCH][CHUNKS][CDIM];
__device__ float g_agg[BATCH][CDIM];

// ---------------------------------------------------------------------------
// Kernel 1: partial column sums (R4 measured-best config).
// grid (BATCH, CHUNKS) = 800 blocks, 256 thr. Thread t: float4-column
// (t&63), row-group (t>>6). Main loop rows [0,96) in pairs, tail row 96+rg.
// ---------------------------------------------------------------------------
__global__ void col_sum_kernel(const float* __restrict__ x) {
    const int b = blockIdx.x;
    const int ch = blockIdx.y;
    const int t = threadIdx.x;
    const int qc = t & 63;       // float4 column 0..63
    const int rg = t >> 6;       // row group 0..3

    const float4* base = (const float4*)(x
        + ((size_t)b * NROWS + (size_t)ch * ROWS_PER_CHUNK) * CDIM) + qc;

    float4 acc0 = make_float4(0.f, 0.f, 0.f, 0.f);
    float4 acc1 = make_float4(0.f, 0.f, 0.f, 0.f);
#pragma unroll
    for (int r = 0; r < 96; r += 8) {
        float4 v0 = base[(size_t)(r + rg) * 64];
        float4 v1 = base[(size_t)(r + rg + 4) * 64];
        acc0.x += v0.x; acc0.y += v0.y; acc0.z += v0.z; acc0.w += v0.w;
        acc1.x += v1.x; acc1.y += v1.y; acc1.z += v1.z; acc1.w += v1.w;
    }
    {
        float4 v0 = base[(size_t)(96 + rg) * 64];
        acc0.x += v0.x; acc0.y += v0.y; acc0.z += v0.z; acc0.w += v0.w;
    }
    acc0.x += acc1.x; acc0.y += acc1.y; acc0.z += acc1.z; acc0.w += acc1.w;

    __shared__ float4 sh[256];
    sh[t] = acc0;
    __syncthreads();
    if (t < 64) {
        float4 a = sh[t];
        float4 c1 = sh[t + 64];
        float4 c2 = sh[t + 128];
        float4 c3 = sh[t + 192];
        a.x += c1.x + c2.x + c3.x;
        a.y += c1.y + c2.y + c3.y;
        a.z += c1.z + c2.z + c3.z;
        a.w += c1.w + c2.w + c3.w;
        ((float4*)&g_partial[b][ch][0])[t] = a;
    }
}

// ---------------------------------------------------------------------------
// Kernel 2: finish mean + tiny GEMM  agg[b][c] = dot(mean[b,:], W[c,:]) + bias
// ---------------------------------------------------------------------------
__global__ void mean_gemm_kernel(const float* __restrict__ W,
                                 const float* __restrict__ bias) {
    const int b = blockIdx.x;
    const int t = threadIdx.x;
    __shared__ float smean[CDIM];

    float s = 0.0f;
#pragma unroll 10
    for (int j = 0; j < CHUNKS; ++j) s += g_partial[b][j][t];
    smean[t] = s * (1.0f / (float)NROWS);
    __syncthreads();

    const int warp = t >> 5;
    const int lane = t & 31;
    for (int c = warp; c < CDIM; c += 8) {
        const float* wr = W + (size_t)c * CDIM;
        float d = 0.0f;
#pragma unroll
        for (int k = lane; k < CDIM; k += 32) {
            d += wr[k] * smean[k];
        }
#pragma unroll
        for (int off = 16; off > 0; off >>= 1)
            d += __shfl_down_sync(0xffffffffu, d, off);
        if (lane == 0) g_agg[b][c] = d + bias[c];
    }
}

// ---------------------------------------------------------------------------
// Kernel 3: fused residual + LayerNorm, software-pipelined.
// Block = 256 threads = 8 warps, 80 rows per block (10 rows per warp,
// 5 iterations of 2 rows). Next iteration's 4 loads are issued before the
// current iteration's compute+store, keeping sustained MLP=4 per lane.
// 10000 = 80*125 so no block crosses a batch boundary. grid = 1000.
// ---------------------------------------------------------------------------
__global__ void resid_ln_kernel(const float* __restrict__ x,
                                const float* __restrict__ gamma,
                                const float* __restrict__ beta,
                                float* __restrict__ out) {
    const int t = threadIdx.x;
    const int warp = t >> 5;
    const int lane = t & 31;
    const long blockRow0 = (long)blockIdx.x * 80;
    const int b = (int)(blockRow0 / NROWS);   // uniform within block

    __shared__ float sh_agg[CDIM];
    __shared__ float sh_g[CDIM];
    __shared__ float sh_b[CDIM];
    sh_agg[t] = g_agg[b][t];
    sh_g[t] = gamma[t];
    sh_b[t] = beta[t];
    __syncthreads();

    const float4 ag0 = ((const float4*)sh_agg)[lane * 2 + 0];
    const float4 ag1 = ((const float4*)sh_agg)[lane * 2 + 1];
    const float4 g0 = ((const float4*)sh_g)[lane * 2 + 0];
    const float4 g1 = ((const float4*)sh_g)[lane * 2 + 1];
    const float4 b0 = ((const float4*)sh_b)[lane * 2 + 0];
    const float4 b1 = ((const float4*)sh_b)[lane * 2 + 1];

    const long row0 = blockRow0 + (long)warp * 10;
    const int li = lane * 2;

    // Prologue: loads for rows row0, row0+1
    float4 c00, c01, c10, c11;
    {
        const float4* xr0 = (const float4*)(x + row0 * (long)CDIM);
        const float4* xr1 = (const float4*)(x + (row0 + 1) * (long)CDIM);
        c00 = xr0[li]; c01 = xr0[li + 1];
        c10 = xr1[li]; c11 = xr1[li + 1];
    }

#pragma unroll
    for (int it = 0; it < 5; ++it) {
        // Issue next iteration's loads first (sustained MLP)
        float4 n00, n01, n10, n11;
        if (it < 4) {
            const long r = row0 + 2 * (it + 1);
            const float4* xr0 = (const float4*)(x + r * (long)CDIM);
            const float4* xr1 = (const float4*)(x + (r + 1) * (long)CDIM);
            n00 = xr0[li]; n01 = xr0[li + 1];
            n10 = xr1[li]; n11 = xr1[li + 1];
        }

        // Compute current two rows
        float ya[8], yb[8];
        ya[0] = c00.x + ag0.x; ya[1] = c00.y + ag0.y;
        ya[2] = c00.z + ag0.z; ya[3] = c00.w + ag0.w;
        ya[4] = c01.x + ag1.x; ya[5] = c01.y + ag1.y;
        ya[6] = c01.z + ag1.z; ya[7] = c01.w + ag1.w;
        yb[0] = c10.x + ag0.x; yb[1] = c10.y + ag0.y;
        yb[2] = c10.z + ag0.z; yb[3] = c10.w + ag0.w;
        yb[4] = c11.x + ag1.x; yb[5] = c11.y + ag1.y;
        yb[6] = c11.z + ag1.z; yb[7] = c11.w + ag1.w;

        float s0 = 0.f, ss0 = 0.f, s1 = 0.f, ss1 = 0.f;
#pragma unroll
        for (int i = 0; i < 8; ++i) {
            s0 += ya[i]; ss0 += ya[i] * ya[i];
            s1 += yb[i]; ss1 += yb[i] * yb[i];
        }
#pragma unroll
        for (int off = 16; off > 0; off >>= 1) {
            s0  += __shfl_xor_sync(0xffffffffu, s0, off);
            ss0 += __shfl_xor_sync(0xffffffffu, ss0, off);
            s1  += __shfl_xor_sync(0xffffffffu, s1, off);
            ss1 += __shfl_xor_sync(0xffffffffu, ss1, off);
        }

        const float inv = 1.0f / (float)CDIM;
        const float mu0 = s0 * inv;
        const float mu1 = s1 * inv;
        const float r0 = rsqrtf(ss0 * inv - mu0 * mu0 + LN_EPS);
        const float r1 = rsqrtf(ss1 * inv - mu1 * mu1 + LN_EPS);

        const long rcur = row0 + 2 * it;
        float4* or0 = (float4*)(out + rcur * (long)CDIM);
        float4* or1 = (float4*)(out + (rcur + 1) * (long)CDIM);
        float4 o;
        o.x = (ya[0] - mu0) * r0 * g0.x + b0.x;
        o.y = (ya[1] - mu0) * r0 * g0.y + b0.y;
        o.z = (ya[2] - mu0) * r0 * g0.z + b0.z;
        o.w = (ya[3] - mu0) * r0 * g0.w + b0.w;
        or0[li] = o;
        o.x = (ya[4] - mu0) * r0 * g1.x + b1.x;
        o.y = (ya[5] - mu0) * r0 * g1.y + b1.y;
        o.z = (ya[6] - mu0) * r0 * g1.z + b1.z;
        o.w = (ya[7] - mu0) * r0 * g1.w + b1.w;
        or0[li + 1] = o;
        o.x = (yb[0] - mu1) * r1 * g0.x + b0.x;
        o.y = (yb[1] - mu1) * r1 * g0.y + b0.y;
        o.z = (yb[2] - mu1) * r1 * g0.z + b0.z;
        o.w = (yb[3] - mu1) * r1 * g0.w + b0.w;
        or1[li] = o;
        o.x = (yb[4] - mu1) * r1 * g1.x + b1.x;
        o.y = (yb[5] - mu1) * r1 * g1.y + b1.y;
        o.z = (yb[6] - mu1) * r1 * g1.z + b1.z;
        o.w = (yb[7] - mu1) * r1 * g1.w + b1.w;
        or1[li + 1] = o;

        // Rotate pipeline
        c00 = n00; c01 = n01; c10 = n10; c11 = n11;
    }
}

extern "C" void kernel_launch(void* const* d_in, const int* in_sizes, int n_in,
                              void* d_out, int out_size) {
    const float* x     = (const float*)d_in[0];
    const float* W     = (const float*)d_in[1];
    const float* bias  = (const float*)d_in[2];
    const float* gamma = (const float*)d_in[3];
    const float* beta  = (const float*)d_in[4];
    float* out = (float*)d_out;

    dim3 g1(BATCH, CHUNKS);
    col_sum_kernel<<<g1, 256>>>(x);
    mean_gemm_kernel<<<BATCH, CDIM>>>(W, bias);
    resid_ln_kernel<<<(BATCH * NROWS) / 80, 256>>>(x, gamma, beta, out);
}